// round 13
// baseline (speedup 1.0000x reference)
#include <cuda_runtime.h>
#include <cuda_bf16.h>
#include <cstdint>

#define N_MAX  50000
#define E_MAX  1000000
#define C_IN   128
#define C_HID  128
#define C_OUT  64

#define SCAN_TILE 1024          // elements per scan block

// ---------------- scratch (device globals; no allocations) ----------------
__device__ __align__(16) float g_h1  [N_MAX * C_HID];   // x @ W1 (RAW, unscaled)
__device__ __align__(16) float g_agg1[N_MAX * C_HID];   // aggregated layer-1
__device__ __align__(16) float g_h2  [N_MAX * C_OUT];   // (relu(agg1+b1) @ W2eff) * dinv
__device__ float g_dinv[N_MAX];
__device__ __align__(16) int g_indeg[N_MAX];   // edge in-degree (no self loop)
__device__ int   g_cursor[N_MAX];
__device__ __align__(16) int g_rowstart[N_MAX + 4];  // CSR (by dst) offsets
__device__ int   g_csrc[E_MAX];           // CSR src ids
__device__ int   g_bsum[(N_MAX + SCAN_TILE - 1) / SCAN_TILE + 1];
__device__ int   g_boff[(N_MAX + SCAN_TILE - 1) / SCAN_TILE + 1];
__device__ __align__(16) float g_w2eff[C_HID * C_OUT];  // W2 @ (linW_top+linW_bot)
__device__ __align__(16) float g_beff[C_OUT];           // b2 @ W_eff + lin_b
__device__ int   g_is32;                  // 1 if edge_index is int32

// ---------------- edge index fetch (dtype-agnostic, scalar path) ----------
__device__ __forceinline__ int edge_at(const void* ei, long long idx) {
    if (g_is32) return ((const int*)ei)[idx];
    return (int)(((const long long*)ei)[idx]);
}

// ---------------- fold: W2eff = W2 @ W_eff, beff = b2 @ W_eff + lin_b ------
// W_eff[k][j] = linW[k][j] + linW[64+k][j]. One thread per output element.
__global__ void k_fold(const float* __restrict__ W2, const float* __restrict__ b2,
                       const float* __restrict__ linW, const float* __restrict__ linb) {
    int o = blockIdx.x * blockDim.x + threadIdx.x;     // 0 .. 128*64-1
    if (o < C_HID * C_OUT) {
        int i = o >> 6, j = o & 63;
        float s = 0.f;
#pragma unroll 8
        for (int k = 0; k < C_OUT; k++)
            s += W2[i * C_OUT + k] * (linW[k * C_OUT + j] + linW[(k + C_OUT) * C_OUT + j]);
        g_w2eff[o] = s;
    }
    if (o < C_OUT) {                                    // beff
        int j = o;
        float s = linb[j];
#pragma unroll 8
        for (int k = 0; k < C_OUT; k++)
            s += b2[k] * (linW[k * C_OUT + j] + linW[(k + C_OUT) * C_OUT + j]);
        g_beff[j] = s;
    }
}

// ---------------- init: zero counters + dtype detect -----------------------
__global__ void k_init(const void* __restrict__ ei, int E, int n) {
    int i = blockIdx.x * blockDim.x + threadIdx.x;
    if (i < n) { g_indeg[i] = 0; g_cursor[i] = 0; }
    if (blockIdx.x == 0) {
        __shared__ int bad;
        if (threadIdx.x == 0) bad = 0;
        __syncthreads();
        const long long* p = (const long long*)ei;
        int limit = E < 4096 ? E : 4096;
        for (int t = threadIdx.x; t < limit; t += blockDim.x) {
            long long v = p[t];
            if (v < 0 || v >= (long long)n) bad = 1;
        }
        __syncthreads();
        if (threadIdx.x == 0) g_is32 = bad;
    }
}

// ---------------- degree count: int4 vector path, 8 edges/thread -----------
__global__ void k_deg_count(const void* __restrict__ ei, int E, int n) {
    int t = blockIdx.x * blockDim.x + threadIdx.x;
    if (g_is32 && (E & 3) == 0) {
        const int4* d4 = (const int4*)((const int*)ei + E);
        int nv = E >> 2;
#pragma unroll
        for (int j = 0; j < 2; j++) {
            int i = t * 2 + j;
            if (i < nv) {
                int4 v = d4[i];
                if ((unsigned)v.x < (unsigned)n) atomicAdd(&g_indeg[v.x], 1);
                if ((unsigned)v.y < (unsigned)n) atomicAdd(&g_indeg[v.y], 1);
                if ((unsigned)v.z < (unsigned)n) atomicAdd(&g_indeg[v.z], 1);
                if ((unsigned)v.w < (unsigned)n) atomicAdd(&g_indeg[v.w], 1);
            }
        }
    } else {
        long long e0 = (long long)t * 8;
        for (int j = 0; j < 8 && e0 + j < E; j++) {
            int d = edge_at(ei, (long long)E + e0 + j);
            if ((unsigned)d < (unsigned)n) atomicAdd(&g_indeg[d], 1);
        }
    }
}

// ---------------- 3-kernel grid scan over indeg -----------------------------
__global__ void k_scan1(int n) {
    __shared__ int wsum[8];
    __shared__ int woff[8];
    const int tid = threadIdx.x;
    const int lane = tid & 31, wid = tid >> 5;
    const int base = blockIdx.x * SCAN_TILE;
    const int i0 = base + tid * 4;

    int4 v = make_int4(0, 0, 0, 0);
    if (i0 + 3 < n) v = *(const int4*)&g_indeg[i0];
    else {
        if (i0 + 0 < n) v.x = g_indeg[i0 + 0];
        if (i0 + 1 < n) v.y = g_indeg[i0 + 1];
        if (i0 + 2 < n) v.z = g_indeg[i0 + 2];
        if (i0 + 3 < n) v.w = g_indeg[i0 + 3];
    }
    int tot = v.x + v.y + v.z + v.w;

    int inc = tot;
#pragma unroll
    for (int off = 1; off < 32; off <<= 1) {
        int o = __shfl_up_sync(0xffffffffu, inc, off);
        if (lane >= off) inc += o;
    }
    if (lane == 31) wsum[wid] = inc;
    __syncthreads();
    if (wid == 0) {
        int s = (lane < 8) ? wsum[lane] : 0;
#pragma unroll
        for (int off = 1; off < 8; off <<= 1) {
            int o = __shfl_up_sync(0xffffffffu, s, off);
            if (lane >= off) s += o;
        }
        if (lane < 8) woff[lane] = s - wsum[lane];
        if (lane == 7) g_bsum[blockIdx.x] = s;
    }
    __syncthreads();

    int excl = woff[wid] + (inc - tot);
    if (i0 + 0 < n) { g_rowstart[i0 + 0] = excl;                     g_dinv[i0 + 0] = rsqrtf((float)(v.x + 1)); }
    if (i0 + 1 < n) { g_rowstart[i0 + 1] = excl + v.x;               g_dinv[i0 + 1] = rsqrtf((float)(v.y + 1)); }
    if (i0 + 2 < n) { g_rowstart[i0 + 2] = excl + v.x + v.y;         g_dinv[i0 + 2] = rsqrtf((float)(v.z + 1)); }
    if (i0 + 3 < n) { g_rowstart[i0 + 3] = excl + v.x + v.y + v.z;   g_dinv[i0 + 3] = rsqrtf((float)(v.w + 1)); }
}

__global__ void k_scan2(int nb, int n) {
    __shared__ int s[256];
    const int tid = threadIdx.x;
    s[tid] = (tid < nb) ? g_bsum[tid] : 0;
    __syncthreads();
    for (int off = 1; off < 256; off <<= 1) {
        int v = (tid >= off) ? s[tid - off] : 0;
        __syncthreads();
        s[tid] += v;
        __syncthreads();
    }
    if (tid < nb) g_boff[tid] = tid ? s[tid - 1] : 0;
    if (tid == 255) g_rowstart[n] = s[255];
}

__global__ void k_scan3(int n) {
    int off = g_boff[blockIdx.x];
    int i0 = blockIdx.x * SCAN_TILE + threadIdx.x * 4;
    if (i0 + 3 < n) {
        int4 r = *(const int4*)&g_rowstart[i0];
        r.x += off; r.y += off; r.z += off; r.w += off;
        *(int4*)&g_rowstart[i0] = r;
    } else {
        for (int j = 0; j < 4 && i0 + j < n; j++) g_rowstart[i0 + j] += off;
    }
}

// ---------------- CSR fill: int4 vector path, 4 edges/thread ---------------
__device__ __forceinline__ void fill_one(int s, int d, int n) {
    if ((unsigned)s >= (unsigned)n || (unsigned)d >= (unsigned)n) return;
    int pos = atomicAdd(&g_cursor[d], 1);
    int idx = g_rowstart[d] + pos;
    if (idx < E_MAX) g_csrc[idx] = s;
}

__global__ void k_fill(const void* __restrict__ ei, int E, int n) {
    int t = blockIdx.x * blockDim.x + threadIdx.x;
    if (g_is32 && (E & 3) == 0) {
        const int4* s4 = (const int4*)ei;
        const int4* d4 = (const int4*)((const int*)ei + E);
        if (t < (E >> 2)) {
            int4 s = s4[t];
            int4 d = d4[t];
            fill_one(s.x, d.x, n);
            fill_one(s.y, d.y, n);
            fill_one(s.z, d.z, n);
            fill_one(s.w, d.w, n);
        }
    } else {
        long long e0 = (long long)t * 4;
        for (int j = 0; j < 4 && e0 + j < E; j++) {
            int s = edge_at(ei, e0 + j);
            int d = edge_at(ei, (long long)E + e0 + j);
            fill_one(s, d, n);
        }
    }
}

// ============ bf16x3 tensor-core GEMM via mma.sync (m16n8k16) ==============
__device__ __forceinline__ uint32_t pack_hi(float x, float y) {
    __nv_bfloat16 a = __float2bfloat16(x), b = __float2bfloat16(y);
    return ((uint32_t)__bfloat16_as_ushort(b) << 16) | __bfloat16_as_ushort(a);
}
__device__ __forceinline__ uint32_t pack_lo(float x, float y) {
    __nv_bfloat16 a = __float2bfloat16(x), b = __float2bfloat16(y);
    float rx = x - __bfloat162float(a), ry = y - __bfloat162float(b);
    __nv_bfloat16 c = __float2bfloat16(rx), d = __float2bfloat16(ry);
    return ((uint32_t)__bfloat16_as_ushort(d) << 16) | __bfloat16_as_ushort(c);
}

__device__ __forceinline__ void mma_bf16(float* d, uint32_t a0, uint32_t a1,
                                         uint32_t a2, uint32_t a3,
                                         uint32_t b0, uint32_t b1) {
    asm volatile(
        "mma.sync.aligned.m16n8k16.row.col.f32.bf16.bf16.f32 "
        "{%0,%1,%2,%3}, {%4,%5,%6,%7}, {%8,%9}, {%0,%1,%2,%3};"
        : "+f"(d[0]), "+f"(d[1]), "+f"(d[2]), "+f"(d[3])
        : "r"(a0), "r"(a1), "r"(a2), "r"(a3), "r"(b0), "r"(b1));
}

// b_from_fold: use g_w2eff as B. a_from_agg1: A = g_agg1. c_sel: 0->h1, 1->h2.
template <int N, bool RELU_BIAS, bool SCALE>
__global__ void __launch_bounds__(256)
k_gemm_mma(const float* __restrict__ Ain, const float* __restrict__ Bin,
           const float* __restrict__ bias, int a_from_agg1, int b_from_fold,
           int c_sel, int M) {
    constexpr int LD = N + 8;
    constexpr int NT = N / 8;
    __shared__ uint32_t sBh[32][LD];
    __shared__ uint32_t sBl[32][LD];

    const float* A = a_from_agg1 ? g_agg1 : Ain;
    const float* Bg = b_from_fold ? g_w2eff : Bin;
    float* C = c_sel ? g_h2 : g_h1;

    const int tid = threadIdx.x;
    const int warp = tid >> 5, lane = tid & 31;
    const int g = lane >> 2, q = lane & 3;
    const int row0 = blockIdx.x * 128 + warp * 16 + g;
    const int row1 = row0 + 8;
    const bool v0 = row0 < M, v1 = row1 < M;

    float acc[NT][4];
#pragma unroll
    for (int c = 0; c < NT; c++)
#pragma unroll
        for (int i = 0; i < 4; i++) acc[c][i] = 0.f;

    const float* ar0 = A + (size_t)row0 * 128;
    const float* ar1 = A + (size_t)row1 * 128;

    for (int half = 0; half < 2; half++) {
        __syncthreads();
        for (int idx = tid; idx < 64 * N; idx += 256) {
            int k = idx / N;
            int nn = idx - k * N;
            float v = Bg[(size_t)(half * 64 + k) * N + nn];
            __nv_bfloat16 hi = __float2bfloat16(v);
            __nv_bfloat16 lo = __float2bfloat16(v - __bfloat162float(hi));
            ((unsigned short*)&sBh[k >> 1][nn])[k & 1] = __bfloat16_as_ushort(hi);
            ((unsigned short*)&sBl[k >> 1][nn])[k & 1] = __bfloat16_as_ushort(lo);
        }
        __syncthreads();

#pragma unroll
        for (int j = 0; j < 4; j++) {
            const int kb = half * 64 + j * 16;
            float2 p00 = make_float2(0.f, 0.f), p01 = p00, p10 = p00, p11 = p00;
            if (v0) { p00 = *(const float2*)(ar0 + kb + 2 * q);
                      p01 = *(const float2*)(ar0 + kb + 2 * q + 8); }
            if (v1) { p10 = *(const float2*)(ar1 + kb + 2 * q);
                      p11 = *(const float2*)(ar1 + kb + 2 * q + 8); }
            if (RELU_BIAS) {
                float2 bA = *(const float2*)(bias + kb + 2 * q);
                float2 bB = *(const float2*)(bias + kb + 2 * q + 8);
                p00.x = fmaxf(p00.x + bA.x, 0.f); p00.y = fmaxf(p00.y + bA.y, 0.f);
                p01.x = fmaxf(p01.x + bB.x, 0.f); p01.y = fmaxf(p01.y + bB.y, 0.f);
                p10.x = fmaxf(p10.x + bA.x, 0.f); p10.y = fmaxf(p10.y + bA.y, 0.f);
                p11.x = fmaxf(p11.x + bB.x, 0.f); p11.y = fmaxf(p11.y + bB.y, 0.f);
            }
            uint32_t ah0 = pack_hi(p00.x, p00.y), al0 = pack_lo(p00.x, p00.y);
            uint32_t ah1 = pack_hi(p10.x, p10.y), al1 = pack_lo(p10.x, p10.y);
            uint32_t ah2 = pack_hi(p01.x, p01.y), al2 = pack_lo(p01.x, p01.y);
            uint32_t ah3 = pack_hi(p11.x, p11.y), al3 = pack_lo(p11.x, p11.y);

            const int kp0 = j * 8 + q, kp1 = kp0 + 4;
#pragma unroll
            for (int c = 0; c < NT; c++) {
                int nn = c * 8 + g;
                uint32_t b0h = sBh[kp0][nn];
                uint32_t b1h = sBh[kp1][nn];
                uint32_t b0l = sBl[kp0][nn];
                uint32_t b1l = sBl[kp1][nn];
                mma_bf16(acc[c], ah0, ah1, ah2, ah3, b0h, b1h);
                mma_bf16(acc[c], ah0, ah1, ah2, ah3, b0l, b1l);
                mma_bf16(acc[c], al0, al1, al2, al3, b0h, b1h);
            }
        }
    }

    float s0 = 1.f, s1 = 1.f;
    if (SCALE) {
        s0 = v0 ? g_dinv[row0] : 0.f;
        s1 = v1 ? g_dinv[row1] : 0.f;
    }
#pragma unroll
    for (int c = 0; c < NT; c++) {
        int col = c * 8 + 2 * q;
        if (v0) *(float2*)(C + (size_t)row0 * N + col) =
            make_float2(acc[c][0] * s0, acc[c][1] * s0);
        if (v1) *(float2*)(C + (size_t)row1 * N + col) =
            make_float2(acc[c][2] * s1, acc[c][3] * s1);
    }
}

// ---------------- CSR aggregation layer 1 (no atomics) ---------------------
// h1 RAW; agg1[d] = dinv[d]*(dinv[d]*h1[d] + sum_e dinv[s]*h1[s]).
__global__ void k_agg128(int n) {
    const int lane = threadIdx.x & 31;
    const int warp = threadIdx.x >> 5;
    int node = blockIdx.x * (blockDim.x >> 5) + warp;
    if (node >= n) return;
    const float4* __restrict__ hv = (const float4*)g_h1;
    const int* __restrict__ csrc = g_csrc;
    const float* __restrict__ dinv = g_dinv;

    float dd = dinv[node];
    float4 self = hv[(size_t)node * 32 + lane];
    float4 acc;
    acc.x = self.x * dd; acc.y = self.y * dd;
    acc.z = self.z * dd; acc.w = self.w * dd;

    int e = g_rowstart[node], end = g_rowstart[node + 1];
    for (; e + 4 <= end; e += 4) {
        int s0 = csrc[e], s1 = csrc[e + 1], s2 = csrc[e + 2], s3 = csrc[e + 3];
        float c0 = dinv[s0], c1 = dinv[s1], c2 = dinv[s2], c3 = dinv[s3];
        float4 v0 = hv[(size_t)s0 * 32 + lane];
        float4 v1 = hv[(size_t)s1 * 32 + lane];
        float4 v2 = hv[(size_t)s2 * 32 + lane];
        float4 v3 = hv[(size_t)s3 * 32 + lane];
        acc.x += v0.x * c0 + v1.x * c1 + v2.x * c2 + v3.x * c3;
        acc.y += v0.y * c0 + v1.y * c1 + v2.y * c2 + v3.y * c3;
        acc.z += v0.z * c0 + v1.z * c1 + v2.z * c2 + v3.z * c3;
        acc.w += v0.w * c0 + v1.w * c1 + v2.w * c2 + v3.w * c3;
    }
    for (; e < end; e++) {
        int s0 = csrc[e];
        float c0 = dinv[s0];
        float4 v = hv[(size_t)s0 * 32 + lane];
        acc.x += v.x * c0; acc.y += v.y * c0;
        acc.z += v.z * c0; acc.w += v.w * c0;
    }
    acc.x *= dd; acc.y *= dd; acc.z *= dd; acc.w *= dd;
    ((float4*)g_agg1)[(size_t)node * 32 + lane] = acc;
}

// -------- FUSED layer-2 aggregation + beff + log_softmax -> out ------------
// h2 = (relu(agg1+b1) @ W2eff)*dinv (pre-scaled). Half-warp per node; lane16
// holds float4 (features 4*lane16..+3). logits = dinv[d]*(h2[d]+sum h2[s]) + beff.
__global__ void k_aggout(float* __restrict__ out, int n) {
    const int lane16 = threadIdx.x & 15;
    const int half = threadIdx.x >> 4;
    int node = blockIdx.x * (blockDim.x >> 4) + half;
    if (node >= n) return;
    const float4* __restrict__ hv = (const float4*)g_h2;
    const int* __restrict__ csrc = g_csrc;

    float4 acc = hv[(size_t)node * 16 + lane16];   // self (pre-scaled)
    int e = g_rowstart[node], end = g_rowstart[node + 1];
    for (; e + 4 <= end; e += 4) {
        int s0 = csrc[e], s1 = csrc[e + 1], s2 = csrc[e + 2], s3 = csrc[e + 3];
        float4 v0 = hv[(size_t)s0 * 16 + lane16];
        float4 v1 = hv[(size_t)s1 * 16 + lane16];
        float4 v2 = hv[(size_t)s2 * 16 + lane16];
        float4 v3 = hv[(size_t)s3 * 16 + lane16];
        acc.x += (v0.x + v1.x) + (v2.x + v3.x);
        acc.y += (v0.y + v1.y) + (v2.y + v3.y);
        acc.z += (v0.z + v1.z) + (v2.z + v3.z);
        acc.w += (v0.w + v1.w) + (v2.w + v3.w);
    }
    for (; e < end; e++) {
        float4 v = hv[(size_t)csrc[e] * 16 + lane16];
        acc.x += v.x; acc.y += v.y; acc.z += v.z; acc.w += v.w;
    }
    float dd = g_dinv[node];
    float4 be = ((const float4*)g_beff)[lane16];
    float4 lg;
    lg.x = acc.x * dd + be.x;
    lg.y = acc.y * dd + be.y;
    lg.z = acc.z * dd + be.z;
    lg.w = acc.w * dd + be.w;

    // log_softmax across the 64 logits held by this 16-lane group
    float m = fmaxf(fmaxf(lg.x, lg.y), fmaxf(lg.z, lg.w));
#pragma unroll
    for (int off = 8; off; off >>= 1)
        m = fmaxf(m, __shfl_xor_sync(0xffffffffu, m, off, 16));
    float s = expf(lg.x - m) + expf(lg.y - m) + expf(lg.z - m) + expf(lg.w - m);
#pragma unroll
    for (int off = 8; off; off >>= 1)
        s += __shfl_xor_sync(0xffffffffu, s, off, 16);
    float lse = m + logf(s);
    float4 o = make_float4(lg.x - lse, lg.y - lse, lg.z - lse, lg.w - lse);
    ((float4*)out)[(size_t)node * 16 + lane16] = o;
}

// ---------------- launcher (fork-join graph: gemm1 || CSR build) -----------
extern "C" void kernel_launch(void* const* d_in, const int* in_sizes, int n_in,
                              void* d_out, int out_size) {
    const float* x    = (const float*)d_in[0];
    const void*  ei   = d_in[1];
    const float* W1   = (const float*)d_in[2];
    const float* b1   = (const float*)d_in[3];
    const float* W2   = (const float*)d_in[4];
    const float* b2   = (const float*)d_in[5];
    const float* linW = (const float*)d_in[6];
    const float* linb = (const float*)d_in[7];
    float* out = (float*)d_out;

    const int n = in_sizes[0] / C_IN;
    const int E = in_sizes[1] / 2;
    const int nb = (n + SCAN_TILE - 1) / SCAN_TILE;

    cudaStream_t s2;
    cudaEvent_t evFork, evJoin;
    cudaStreamCreateWithFlags(&s2, cudaStreamNonBlocking);
    cudaEventCreateWithFlags(&evFork, cudaEventDisableTiming);
    cudaEventCreateWithFlags(&evJoin, cudaEventDisableTiming);

    // ---- fork: gemm1 (raw h1, no dinv dependency) runs on s2
    cudaEventRecord(evFork, 0);
    cudaStreamWaitEvent(s2, evFork, 0);
    k_gemm_mma<C_HID, false, false><<<(n + 127) / 128, 256, 0, s2>>>(
        x, W1, nullptr, 0, 0, 0, n);
    cudaEventRecord(evJoin, s2);

    // ---- main stream: weight fold + CSR build chain
    k_fold<<<(C_HID * C_OUT + 255) / 256, 256>>>(W2, b2, linW, linb);
    k_init<<<(n + 255) / 256, 256>>>(ei, E, n);
    k_deg_count<<<(E + 2047) / 2048, 256>>>(ei, E, n);
    k_scan1<<<nb, 256>>>(n);
    k_scan2<<<1, 256>>>(nb, n);
    k_scan3<<<nb, 256>>>(n);
    k_fill<<<(E + 1023) / 1024, 256>>>(ei, E, n);

    // ---- join: aggregation needs h1 + CSR + dinv
    cudaStreamWaitEvent(0, evJoin, 0);
    k_agg128<<<(n + 7) / 8, 256>>>(n);

    // layer 2: h2 = (relu(agg1+b1) @ W2eff)*dinv ; fused agg + softmax -> out
    k_gemm_mma<C_OUT, true, true><<<(n + 127) / 128, 256>>>(
        nullptr, nullptr, b1, 1, 1, 1, n);
    k_aggout<<<(n + 15) / 16, 256>>>(out, n);

    cudaEventDestroy(evFork);
    cudaEventDestroy(evJoin);
    cudaStreamDestroy(s2);
}

// round 15
// speedup vs baseline: 1.3499x; 1.3499x over previous
#include <cuda_runtime.h>
#include <cuda_bf16.h>
#include <cstdint>

#define N_MAX  50000
#define E_MAX  1000000
#define C_IN   128
#define C_HID  128
#define C_OUT  64

#define SCAN_TILE 1024          // elements per scan block

// ---------------- scratch (device globals; no allocations) ----------------
__device__ __align__(16) float g_h1  [N_MAX * C_HID];   // x @ W1 (RAW, unscaled)
__device__ __align__(16) float g_agg1[N_MAX * C_HID];   // aggregated layer-1
__device__ __align__(16) float g_h2  [N_MAX * C_OUT];   // (relu(agg1+b1) @ W2eff) * dinv
__device__ float g_dinv[N_MAX];
__device__ __align__(16) int g_indeg[N_MAX];   // edge in-degree (no self loop)
__device__ int   g_cursor[N_MAX];
__device__ __align__(16) int g_rowstart[N_MAX + 4];  // CSR (by dst) offsets
__device__ int   g_csrc[E_MAX];           // CSR src ids
__device__ int   g_bsum[(N_MAX + SCAN_TILE - 1) / SCAN_TILE + 1];
__device__ int   g_boff[(N_MAX + SCAN_TILE - 1) / SCAN_TILE + 1];
__device__ __align__(16) float g_w2eff[C_HID * C_OUT];  // W2 @ (linW_top+linW_bot)
__device__ __align__(16) float g_beff[C_OUT];           // b2 @ W_eff + lin_b
__device__ int   g_is32;                  // 1 if edge_index is int32

// ---------------- edge index fetch (dtype-agnostic, scalar path) ----------
__device__ __forceinline__ int edge_at(const void* ei, long long idx) {
    if (g_is32) return ((const int*)ei)[idx];
    return (int)(((const long long*)ei)[idx]);
}

// ---------------- fold: W2eff = W2 @ W_eff, beff = b2 @ W_eff + lin_b ------
// W_eff[k][j] = linW[k][j] + linW[64+k][j]. One thread per output element.
__global__ void k_fold(const float* __restrict__ W2, const float* __restrict__ b2,
                       const float* __restrict__ linW, const float* __restrict__ linb) {
    int o = blockIdx.x * blockDim.x + threadIdx.x;     // 0 .. 128*64-1
    if (o < C_HID * C_OUT) {
        int i = o >> 6, j = o & 63;
        float s = 0.f;
#pragma unroll 8
        for (int k = 0; k < C_OUT; k++)
            s += W2[i * C_OUT + k] * (linW[k * C_OUT + j] + linW[(k + C_OUT) * C_OUT + j]);
        g_w2eff[o] = s;
    }
    if (o < C_OUT) {                                    // beff
        int j = o;
        float s = linb[j];
#pragma unroll 8
        for (int k = 0; k < C_OUT; k++)
            s += b2[k] * (linW[k * C_OUT + j] + linW[(k + C_OUT) * C_OUT + j]);
        g_beff[j] = s;
    }
}

// ---------------- init: zero counters + dtype detect -----------------------
__global__ void k_init(const void* __restrict__ ei, int E, int n) {
    int i = blockIdx.x * blockDim.x + threadIdx.x;
    if (i < n) { g_indeg[i] = 0; g_cursor[i] = 0; }
    if (blockIdx.x == 0) {
        __shared__ int bad;
        if (threadIdx.x == 0) bad = 0;
        __syncthreads();
        const long long* p = (const long long*)ei;
        int limit = E < 4096 ? E : 4096;
        for (int t = threadIdx.x; t < limit; t += blockDim.x) {
            long long v = p[t];
            if (v < 0 || v >= (long long)n) bad = 1;
        }
        __syncthreads();
        if (threadIdx.x == 0) g_is32 = bad;
    }
}

// ---------------- degree count: int4 vector path, 8 edges/thread -----------
__global__ void k_deg_count(const void* __restrict__ ei, int E, int n) {
    int t = blockIdx.x * blockDim.x + threadIdx.x;
    if (g_is32 && (E & 3) == 0) {
        const int4* d4 = (const int4*)((const int*)ei + E);
        int nv = E >> 2;
#pragma unroll
        for (int j = 0; j < 2; j++) {
            int i = t * 2 + j;
            if (i < nv) {
                int4 v = d4[i];
                if ((unsigned)v.x < (unsigned)n) atomicAdd(&g_indeg[v.x], 1);
                if ((unsigned)v.y < (unsigned)n) atomicAdd(&g_indeg[v.y], 1);
                if ((unsigned)v.z < (unsigned)n) atomicAdd(&g_indeg[v.z], 1);
                if ((unsigned)v.w < (unsigned)n) atomicAdd(&g_indeg[v.w], 1);
            }
        }
    } else {
        long long e0 = (long long)t * 8;
        for (int j = 0; j < 8 && e0 + j < E; j++) {
            int d = edge_at(ei, (long long)E + e0 + j);
            if ((unsigned)d < (unsigned)n) atomicAdd(&g_indeg[d], 1);
        }
    }
}

// ---------------- 3-kernel grid scan over indeg -----------------------------
__global__ void k_scan1(int n) {
    __shared__ int wsum[8];
    __shared__ int woff[8];
    const int tid = threadIdx.x;
    const int lane = tid & 31, wid = tid >> 5;
    const int base = blockIdx.x * SCAN_TILE;
    const int i0 = base + tid * 4;

    int4 v = make_int4(0, 0, 0, 0);
    if (i0 + 3 < n) v = *(const int4*)&g_indeg[i0];
    else {
        if (i0 + 0 < n) v.x = g_indeg[i0 + 0];
        if (i0 + 1 < n) v.y = g_indeg[i0 + 1];
        if (i0 + 2 < n) v.z = g_indeg[i0 + 2];
        if (i0 + 3 < n) v.w = g_indeg[i0 + 3];
    }
    int tot = v.x + v.y + v.z + v.w;

    int inc = tot;
#pragma unroll
    for (int off = 1; off < 32; off <<= 1) {
        int o = __shfl_up_sync(0xffffffffu, inc, off);
        if (lane >= off) inc += o;
    }
    if (lane == 31) wsum[wid] = inc;
    __syncthreads();
    if (wid == 0) {
        int s = (lane < 8) ? wsum[lane] : 0;
#pragma unroll
        for (int off = 1; off < 8; off <<= 1) {
            int o = __shfl_up_sync(0xffffffffu, s, off);
            if (lane >= off) s += o;
        }
        if (lane < 8) woff[lane] = s - wsum[lane];
        if (lane == 7) g_bsum[blockIdx.x] = s;
    }
    __syncthreads();

    int excl = woff[wid] + (inc - tot);
    if (i0 + 0 < n) { g_rowstart[i0 + 0] = excl;                     g_dinv[i0 + 0] = rsqrtf((float)(v.x + 1)); }
    if (i0 + 1 < n) { g_rowstart[i0 + 1] = excl + v.x;               g_dinv[i0 + 1] = rsqrtf((float)(v.y + 1)); }
    if (i0 + 2 < n) { g_rowstart[i0 + 2] = excl + v.x + v.y;         g_dinv[i0 + 2] = rsqrtf((float)(v.z + 1)); }
    if (i0 + 3 < n) { g_rowstart[i0 + 3] = excl + v.x + v.y + v.z;   g_dinv[i0 + 3] = rsqrtf((float)(v.w + 1)); }
}

__global__ void k_scan2(int nb, int n) {
    __shared__ int s[256];
    const int tid = threadIdx.x;
    s[tid] = (tid < nb) ? g_bsum[tid] : 0;
    __syncthreads();
    for (int off = 1; off < 256; off <<= 1) {
        int v = (tid >= off) ? s[tid - off] : 0;
        __syncthreads();
        s[tid] += v;
        __syncthreads();
    }
    if (tid < nb) g_boff[tid] = tid ? s[tid - 1] : 0;
    if (tid == 255) g_rowstart[n] = s[255];
}

__global__ void k_scan3(int n) {
    int off = g_boff[blockIdx.x];
    int i0 = blockIdx.x * SCAN_TILE + threadIdx.x * 4;
    if (i0 + 3 < n) {
        int4 r = *(const int4*)&g_rowstart[i0];
        r.x += off; r.y += off; r.z += off; r.w += off;
        *(int4*)&g_rowstart[i0] = r;
    } else {
        for (int j = 0; j < 4 && i0 + j < n; j++) g_rowstart[i0 + j] += off;
    }
}

// ---------------- CSR fill: int4 vector path, 4 edges/thread ---------------
__device__ __forceinline__ void fill_one(int s, int d, int n) {
    if ((unsigned)s >= (unsigned)n || (unsigned)d >= (unsigned)n) return;
    int pos = atomicAdd(&g_cursor[d], 1);
    int idx = g_rowstart[d] + pos;
    if (idx < E_MAX) g_csrc[idx] = s;
}

__global__ void k_fill(const void* __restrict__ ei, int E, int n) {
    int t = blockIdx.x * blockDim.x + threadIdx.x;
    if (g_is32 && (E & 3) == 0) {
        const int4* s4 = (const int4*)ei;
        const int4* d4 = (const int4*)((const int*)ei + E);
        if (t < (E >> 2)) {
            int4 s = s4[t];
            int4 d = d4[t];
            fill_one(s.x, d.x, n);
            fill_one(s.y, d.y, n);
            fill_one(s.z, d.z, n);
            fill_one(s.w, d.w, n);
        }
    } else {
        long long e0 = (long long)t * 4;
        for (int j = 0; j < 4 && e0 + j < E; j++) {
            int s = edge_at(ei, e0 + j);
            int d = edge_at(ei, (long long)E + e0 + j);
            fill_one(s, d, n);
        }
    }
}

// ============ bf16x3 tensor-core GEMM via mma.sync (m16n8k16) ==============
__device__ __forceinline__ uint32_t pack_hi(float x, float y) {
    __nv_bfloat16 a = __float2bfloat16(x), b = __float2bfloat16(y);
    return ((uint32_t)__bfloat16_as_ushort(b) << 16) | __bfloat16_as_ushort(a);
}
__device__ __forceinline__ uint32_t pack_lo(float x, float y) {
    __nv_bfloat16 a = __float2bfloat16(x), b = __float2bfloat16(y);
    float rx = x - __bfloat162float(a), ry = y - __bfloat162float(b);
    __nv_bfloat16 c = __float2bfloat16(rx), d = __float2bfloat16(ry);
    return ((uint32_t)__bfloat16_as_ushort(d) << 16) | __bfloat16_as_ushort(c);
}

__device__ __forceinline__ void mma_bf16(float* d, uint32_t a0, uint32_t a1,
                                         uint32_t a2, uint32_t a3,
                                         uint32_t b0, uint32_t b1) {
    asm volatile(
        "mma.sync.aligned.m16n8k16.row.col.f32.bf16.bf16.f32 "
        "{%0,%1,%2,%3}, {%4,%5,%6,%7}, {%8,%9}, {%0,%1,%2,%3};"
        : "+f"(d[0]), "+f"(d[1]), "+f"(d[2]), "+f"(d[3])
        : "r"(a0), "r"(a1), "r"(a2), "r"(a3), "r"(b0), "r"(b1));
}

// b_from_fold: use g_w2eff as B. a_from_agg1: A = g_agg1. c_sel: 0->h1, 1->h2.
template <int N, bool RELU_BIAS, bool SCALE>
__global__ void __launch_bounds__(256)
k_gemm_mma(const float* __restrict__ Ain, const float* __restrict__ Bin,
           const float* __restrict__ bias, int a_from_agg1, int b_from_fold,
           int c_sel, int M) {
    constexpr int LD = N + 8;
    constexpr int NT = N / 8;
    __shared__ uint32_t sBh[32][LD];
    __shared__ uint32_t sBl[32][LD];

    const float* A = a_from_agg1 ? g_agg1 : Ain;
    const float* Bg = b_from_fold ? g_w2eff : Bin;
    float* C = c_sel ? g_h2 : g_h1;

    const int tid = threadIdx.x;
    const int warp = tid >> 5, lane = tid & 31;
    const int g = lane >> 2, q = lane & 3;
    const int row0 = blockIdx.x * 128 + warp * 16 + g;
    const int row1 = row0 + 8;
    const bool v0 = row0 < M, v1 = row1 < M;

    float acc[NT][4];
#pragma unroll
    for (int c = 0; c < NT; c++)
#pragma unroll
        for (int i = 0; i < 4; i++) acc[c][i] = 0.f;

    const float* ar0 = A + (size_t)row0 * 128;
    const float* ar1 = A + (size_t)row1 * 128;

    for (int half = 0; half < 2; half++) {
        __syncthreads();
        for (int idx = tid; idx < 64 * N; idx += 256) {
            int k = idx / N;
            int nn = idx - k * N;
            float v = Bg[(size_t)(half * 64 + k) * N + nn];
            __nv_bfloat16 hi = __float2bfloat16(v);
            __nv_bfloat16 lo = __float2bfloat16(v - __bfloat162float(hi));
            ((unsigned short*)&sBh[k >> 1][nn])[k & 1] = __bfloat16_as_ushort(hi);
            ((unsigned short*)&sBl[k >> 1][nn])[k & 1] = __bfloat16_as_ushort(lo);
        }
        __syncthreads();

#pragma unroll
        for (int j = 0; j < 4; j++) {
            const int kb = half * 64 + j * 16;
            float2 p00 = make_float2(0.f, 0.f), p01 = p00, p10 = p00, p11 = p00;
            if (v0) { p00 = *(const float2*)(ar0 + kb + 2 * q);
                      p01 = *(const float2*)(ar0 + kb + 2 * q + 8); }
            if (v1) { p10 = *(const float2*)(ar1 + kb + 2 * q);
                      p11 = *(const float2*)(ar1 + kb + 2 * q + 8); }
            if (RELU_BIAS) {
                float2 bA = *(const float2*)(bias + kb + 2 * q);
                float2 bB = *(const float2*)(bias + kb + 2 * q + 8);
                p00.x = fmaxf(p00.x + bA.x, 0.f); p00.y = fmaxf(p00.y + bA.y, 0.f);
                p01.x = fmaxf(p01.x + bB.x, 0.f); p01.y = fmaxf(p01.y + bB.y, 0.f);
                p10.x = fmaxf(p10.x + bA.x, 0.f); p10.y = fmaxf(p10.y + bA.y, 0.f);
                p11.x = fmaxf(p11.x + bB.x, 0.f); p11.y = fmaxf(p11.y + bB.y, 0.f);
            }
            uint32_t ah0 = pack_hi(p00.x, p00.y), al0 = pack_lo(p00.x, p00.y);
            uint32_t ah1 = pack_hi(p10.x, p10.y), al1 = pack_lo(p10.x, p10.y);
            uint32_t ah2 = pack_hi(p01.x, p01.y), al2 = pack_lo(p01.x, p01.y);
            uint32_t ah3 = pack_hi(p11.x, p11.y), al3 = pack_lo(p11.x, p11.y);

            const int kp0 = j * 8 + q, kp1 = kp0 + 4;
#pragma unroll
            for (int c = 0; c < NT; c++) {
                int nn = c * 8 + g;
                uint32_t b0h = sBh[kp0][nn];
                uint32_t b1h = sBh[kp1][nn];
                uint32_t b0l = sBl[kp0][nn];
                uint32_t b1l = sBl[kp1][nn];
                mma_bf16(acc[c], ah0, ah1, ah2, ah3, b0h, b1h);
                mma_bf16(acc[c], ah0, ah1, ah2, ah3, b0l, b1l);
                mma_bf16(acc[c], al0, al1, al2, al3, b0h, b1h);
            }
        }
    }

    float s0 = 1.f, s1 = 1.f;
    if (SCALE) {
        s0 = v0 ? g_dinv[row0] : 0.f;
        s1 = v1 ? g_dinv[row1] : 0.f;
    }
#pragma unroll
    for (int c = 0; c < NT; c++) {
        int col = c * 8 + 2 * q;
        if (v0) *(float2*)(C + (size_t)row0 * N + col) =
            make_float2(acc[c][0] * s0, acc[c][1] * s0);
        if (v1) *(float2*)(C + (size_t)row1 * N + col) =
            make_float2(acc[c][2] * s1, acc[c][3] * s1);
    }
}

// ---------------- CSR aggregation layer 1 (no atomics) ---------------------
// h1 RAW; agg1[d] = dinv[d]*(dinv[d]*h1[d] + sum_e dinv[s]*h1[s]).
__global__ void k_agg128(int n) {
    const int lane = threadIdx.x & 31;
    const int warp = threadIdx.x >> 5;
    int node = blockIdx.x * (blockDim.x >> 5) + warp;
    if (node >= n) return;
    const float4* __restrict__ hv = (const float4*)g_h1;
    const int* __restrict__ csrc = g_csrc;
    const float* __restrict__ dinv = g_dinv;

    float dd = dinv[node];
    float4 self = hv[(size_t)node * 32 + lane];
    float4 acc;
    acc.x = self.x * dd; acc.y = self.y * dd;
    acc.z = self.z * dd; acc.w = self.w * dd;

    int e = g_rowstart[node], end = g_rowstart[node + 1];
    for (; e + 4 <= end; e += 4) {
        int s0 = csrc[e], s1 = csrc[e + 1], s2 = csrc[e + 2], s3 = csrc[e + 3];
        float c0 = dinv[s0], c1 = dinv[s1], c2 = dinv[s2], c3 = dinv[s3];
        float4 v0 = hv[(size_t)s0 * 32 + lane];
        float4 v1 = hv[(size_t)s1 * 32 + lane];
        float4 v2 = hv[(size_t)s2 * 32 + lane];
        float4 v3 = hv[(size_t)s3 * 32 + lane];
        acc.x += v0.x * c0 + v1.x * c1 + v2.x * c2 + v3.x * c3;
        acc.y += v0.y * c0 + v1.y * c1 + v2.y * c2 + v3.y * c3;
        acc.z += v0.z * c0 + v1.z * c1 + v2.z * c2 + v3.z * c3;
        acc.w += v0.w * c0 + v1.w * c1 + v2.w * c2 + v3.w * c3;
    }
    for (; e < end; e++) {
        int s0 = csrc[e];
        float c0 = dinv[s0];
        float4 v = hv[(size_t)s0 * 32 + lane];
        acc.x += v.x * c0; acc.y += v.y * c0;
        acc.z += v.z * c0; acc.w += v.w * c0;
    }
    acc.x *= dd; acc.y *= dd; acc.z *= dd; acc.w *= dd;
    ((float4*)g_agg1)[(size_t)node * 32 + lane] = acc;
}

// -------- FUSED layer-2 aggregation + beff + log_softmax -> out ------------
// h2 = (relu(agg1+b1) @ W2eff)*dinv (pre-scaled). Half-warp per node; lane16
// holds float4 (features 4*lane16..+3). logits = dinv[d]*(h2[d]+sum h2[s]) + beff.
__global__ void k_aggout(float* __restrict__ out, int n) {
    const int lane16 = threadIdx.x & 15;
    const int half = threadIdx.x >> 4;
    int node = blockIdx.x * (blockDim.x >> 4) + half;
    if (node >= n) return;
    const float4* __restrict__ hv = (const float4*)g_h2;
    const int* __restrict__ csrc = g_csrc;

    float4 acc = hv[(size_t)node * 16 + lane16];   // self (pre-scaled)
    int e = g_rowstart[node], end = g_rowstart[node + 1];
    for (; e + 4 <= end; e += 4) {
        int s0 = csrc[e], s1 = csrc[e + 1], s2 = csrc[e + 2], s3 = csrc[e + 3];
        float4 v0 = hv[(size_t)s0 * 16 + lane16];
        float4 v1 = hv[(size_t)s1 * 16 + lane16];
        float4 v2 = hv[(size_t)s2 * 16 + lane16];
        float4 v3 = hv[(size_t)s3 * 16 + lane16];
        acc.x += (v0.x + v1.x) + (v2.x + v3.x);
        acc.y += (v0.y + v1.y) + (v2.y + v3.y);
        acc.z += (v0.z + v1.z) + (v2.z + v3.z);
        acc.w += (v0.w + v1.w) + (v2.w + v3.w);
    }
    for (; e < end; e++) {
        float4 v = hv[(size_t)csrc[e] * 16 + lane16];
        acc.x += v.x; acc.y += v.y; acc.z += v.z; acc.w += v.w;
    }
    float dd = g_dinv[node];
    float4 be = ((const float4*)g_beff)[lane16];
    float4 lg;
    lg.x = acc.x * dd + be.x;
    lg.y = acc.y * dd + be.y;
    lg.z = acc.z * dd + be.z;
    lg.w = acc.w * dd + be.w;

    // log_softmax across the 64 logits held by this 16-lane group
    float m = fmaxf(fmaxf(lg.x, lg.y), fmaxf(lg.z, lg.w));
#pragma unroll
    for (int off = 8; off; off >>= 1)
        m = fmaxf(m, __shfl_xor_sync(0xffffffffu, m, off, 16));
    float s = expf(lg.x - m) + expf(lg.y - m) + expf(lg.z - m) + expf(lg.w - m);
#pragma unroll
    for (int off = 8; off; off >>= 1)
        s += __shfl_xor_sync(0xffffffffu, s, off, 16);
    float lse = m + logf(s);
    float4 o = make_float4(lg.x - lse, lg.y - lse, lg.z - lse, lg.w - lse);
    ((float4*)out)[(size_t)node * 16 + lane16] = o;
}

// ---------------- launcher (fork-join: [fold+gemm1] || CSR build) ----------
extern "C" void kernel_launch(void* const* d_in, const int* in_sizes, int n_in,
                              void* d_out, int out_size) {
    const float* x    = (const float*)d_in[0];
    const void*  ei   = d_in[1];
    const float* W1   = (const float*)d_in[2];
    const float* b1   = (const float*)d_in[3];
    const float* W2   = (const float*)d_in[4];
    const float* b2   = (const float*)d_in[5];
    const float* linW = (const float*)d_in[6];
    const float* linb = (const float*)d_in[7];
    float* out = (float*)d_out;

    const int n = in_sizes[0] / C_IN;
    const int E = in_sizes[1] / 2;
    const int nb = (n + SCAN_TILE - 1) / SCAN_TILE;

    cudaStream_t s2;
    cudaEvent_t evFork, evJoin;
    cudaStreamCreateWithFlags(&s2, cudaStreamNonBlocking);
    cudaEventCreateWithFlags(&evFork, cudaEventDisableTiming);
    cudaEventCreateWithFlags(&evJoin, cudaEventDisableTiming);

    // ---- fork: weight fold + gemm1 run on s2 (both independent of CSR/deg)
    cudaEventRecord(evFork, 0);
    cudaStreamWaitEvent(s2, evFork, 0);
    k_fold<<<(C_HID * C_OUT + 255) / 256, 256, 0, s2>>>(W2, b2, linW, linb);
    k_gemm_mma<C_HID, false, false><<<(n + 127) / 128, 256, 0, s2>>>(
        x, W1, nullptr, 0, 0, 0, n);
    cudaEventRecord(evJoin, s2);

    // ---- main stream: CSR build chain
    k_init<<<(n + 255) / 256, 256>>>(ei, E, n);
    k_deg_count<<<(E + 2047) / 2048, 256>>>(ei, E, n);
    k_scan1<<<nb, 256>>>(n);
    k_scan2<<<1, 256>>>(nb, n);
    k_scan3<<<nb, 256>>>(n);
    k_fill<<<(E + 1023) / 1024, 256>>>(ei, E, n);

    // ---- join: aggregation needs h1 + CSR + dinv (and fold done on s2)
    cudaStreamWaitEvent(0, evJoin, 0);
    k_agg128<<<(n + 7) / 8, 256>>>(n);

    // layer 2: h2 = (relu(agg1+b1) @ W2eff)*dinv ; fused agg + softmax -> out
    k_gemm_mma<C_OUT, true, true><<<(n + 127) / 128, 256>>>(
        nullptr, nullptr, b1, 1, 1, 1, n);
    k_aggout<<<(n + 15) / 16, 256>>>(out, n);

    cudaEventDestroy(evFork);
    cudaEventDestroy(evJoin);
    cudaStreamDestroy(s2);
}

// round 17
// speedup vs baseline: 1.3804x; 1.0226x over previous
#include <cuda_runtime.h>
#include <cuda_bf16.h>
#include <cuda_fp16.h>
#include <cstdint>

#define N_MAX  50000
#define E_MAX  1000000
#define C_IN   128
#define C_HID  128
#define C_OUT  64

#define SCAN_TILE 1024          // elements per scan block

// ---------------- scratch (device globals; no allocations) ----------------
__device__ __align__(16) __half g_h1[N_MAX * C_HID];    // x @ W1 (RAW), fp16
__device__ __align__(16) float g_agg1[N_MAX * C_HID];   // aggregated layer-1 (fp32)
__device__ __align__(16) float g_h2  [N_MAX * C_OUT];   // (relu(agg1+b1) @ W2eff) * dinv
__device__ float g_dinv[N_MAX];
__device__ __align__(16) int g_indeg[N_MAX];   // edge in-degree (no self loop)
__device__ int   g_cursor[N_MAX];
__device__ __align__(16) int g_rowstart[N_MAX + 4];  // CSR (by dst) offsets
__device__ int   g_csrc[E_MAX];           // CSR src ids
__device__ int   g_bsum[(N_MAX + SCAN_TILE - 1) / SCAN_TILE + 1];
__device__ int   g_boff[(N_MAX + SCAN_TILE - 1) / SCAN_TILE + 1];
__device__ __align__(16) float g_w2eff[C_HID * C_OUT];  // W2 @ (linW_top+linW_bot)
__device__ __align__(16) float g_beff[C_OUT];           // b2 @ W_eff + lin_b
__device__ int   g_is32;                  // 1 if edge_index is int32

// ---------------- edge index fetch (dtype-agnostic, scalar path) ----------
__device__ __forceinline__ int edge_at(const void* ei, long long idx) {
    if (g_is32) return ((const int*)ei)[idx];
    return (int)(((const long long*)ei)[idx]);
}

// ---------------- fold: W2eff = W2 @ W_eff, beff = b2 @ W_eff + lin_b ------
__global__ void k_fold(const float* __restrict__ W2, const float* __restrict__ b2,
                       const float* __restrict__ linW, const float* __restrict__ linb) {
    int o = blockIdx.x * blockDim.x + threadIdx.x;     // 0 .. 128*64-1
    if (o < C_HID * C_OUT) {
        int i = o >> 6, j = o & 63;
        float s = 0.f;
#pragma unroll 8
        for (int k = 0; k < C_OUT; k++)
            s += W2[i * C_OUT + k] * (linW[k * C_OUT + j] + linW[(k + C_OUT) * C_OUT + j]);
        g_w2eff[o] = s;
    }
    if (o < C_OUT) {
        int j = o;
        float s = linb[j];
#pragma unroll 8
        for (int k = 0; k < C_OUT; k++)
            s += b2[k] * (linW[k * C_OUT + j] + linW[(k + C_OUT) * C_OUT + j]);
        g_beff[j] = s;
    }
}

// ---------------- init: zero counters + dtype detect -----------------------
__global__ void k_init(const void* __restrict__ ei, int E, int n) {
    int i = blockIdx.x * blockDim.x + threadIdx.x;
    if (i < n) { g_indeg[i] = 0; g_cursor[i] = 0; }
    if (blockIdx.x == 0) {
        __shared__ int bad;
        if (threadIdx.x == 0) bad = 0;
        __syncthreads();
        const long long* p = (const long long*)ei;
        int limit = E < 4096 ? E : 4096;
        for (int t = threadIdx.x; t < limit; t += blockDim.x) {
            long long v = p[t];
            if (v < 0 || v >= (long long)n) bad = 1;
        }
        __syncthreads();
        if (threadIdx.x == 0) g_is32 = bad;
    }
}

// ---------------- degree count: int4 vector path, 8 edges/thread -----------
__global__ void k_deg_count(const void* __restrict__ ei, int E, int n) {
    int t = blockIdx.x * blockDim.x + threadIdx.x;
    if (g_is32 && (E & 3) == 0) {
        const int4* d4 = (const int4*)((const int*)ei + E);
        int nv = E >> 2;
#pragma unroll
        for (int j = 0; j < 2; j++) {
            int i = t * 2 + j;
            if (i < nv) {
                int4 v = d4[i];
                if ((unsigned)v.x < (unsigned)n) atomicAdd(&g_indeg[v.x], 1);
                if ((unsigned)v.y < (unsigned)n) atomicAdd(&g_indeg[v.y], 1);
                if ((unsigned)v.z < (unsigned)n) atomicAdd(&g_indeg[v.z], 1);
                if ((unsigned)v.w < (unsigned)n) atomicAdd(&g_indeg[v.w], 1);
            }
        }
    } else {
        long long e0 = (long long)t * 8;
        for (int j = 0; j < 8 && e0 + j < E; j++) {
            int d = edge_at(ei, (long long)E + e0 + j);
            if ((unsigned)d < (unsigned)n) atomicAdd(&g_indeg[d], 1);
        }
    }
}

// ---------------- 3-kernel grid scan over indeg -----------------------------
__global__ void k_scan1(int n) {
    __shared__ int wsum[8];
    __shared__ int woff[8];
    const int tid = threadIdx.x;
    const int lane = tid & 31, wid = tid >> 5;
    const int base = blockIdx.x * SCAN_TILE;
    const int i0 = base + tid * 4;

    int4 v = make_int4(0, 0, 0, 0);
    if (i0 + 3 < n) v = *(const int4*)&g_indeg[i0];
    else {
        if (i0 + 0 < n) v.x = g_indeg[i0 + 0];
        if (i0 + 1 < n) v.y = g_indeg[i0 + 1];
        if (i0 + 2 < n) v.z = g_indeg[i0 + 2];
        if (i0 + 3 < n) v.w = g_indeg[i0 + 3];
    }
    int tot = v.x + v.y + v.z + v.w;

    int inc = tot;
#pragma unroll
    for (int off = 1; off < 32; off <<= 1) {
        int o = __shfl_up_sync(0xffffffffu, inc, off);
        if (lane >= off) inc += o;
    }
    if (lane == 31) wsum[wid] = inc;
    __syncthreads();
    if (wid == 0) {
        int s = (lane < 8) ? wsum[lane] : 0;
#pragma unroll
        for (int off = 1; off < 8; off <<= 1) {
            int o = __shfl_up_sync(0xffffffffu, s, off);
            if (lane >= off) s += o;
        }
        if (lane < 8) woff[lane] = s - wsum[lane];
        if (lane == 7) g_bsum[blockIdx.x] = s;
    }
    __syncthreads();

    int excl = woff[wid] + (inc - tot);
    if (i0 + 0 < n) { g_rowstart[i0 + 0] = excl;                     g_dinv[i0 + 0] = rsqrtf((float)(v.x + 1)); }
    if (i0 + 1 < n) { g_rowstart[i0 + 1] = excl + v.x;               g_dinv[i0 + 1] = rsqrtf((float)(v.y + 1)); }
    if (i0 + 2 < n) { g_rowstart[i0 + 2] = excl + v.x + v.y;         g_dinv[i0 + 2] = rsqrtf((float)(v.z + 1)); }
    if (i0 + 3 < n) { g_rowstart[i0 + 3] = excl + v.x + v.y + v.z;   g_dinv[i0 + 3] = rsqrtf((float)(v.w + 1)); }
}

__global__ void k_scan2(int nb, int n) {
    __shared__ int s[256];
    const int tid = threadIdx.x;
    s[tid] = (tid < nb) ? g_bsum[tid] : 0;
    __syncthreads();
    for (int off = 1; off < 256; off <<= 1) {
        int v = (tid >= off) ? s[tid - off] : 0;
        __syncthreads();
        s[tid] += v;
        __syncthreads();
    }
    if (tid < nb) g_boff[tid] = tid ? s[tid - 1] : 0;
    if (tid == 255) g_rowstart[n] = s[255];
}

__global__ void k_scan3(int n) {
    int off = g_boff[blockIdx.x];
    int i0 = blockIdx.x * SCAN_TILE + threadIdx.x * 4;
    if (i0 + 3 < n) {
        int4 r = *(const int4*)&g_rowstart[i0];
        r.x += off; r.y += off; r.z += off; r.w += off;
        *(int4*)&g_rowstart[i0] = r;
    } else {
        for (int j = 0; j < 4 && i0 + j < n; j++) g_rowstart[i0 + j] += off;
    }
}

// ---------------- CSR fill: int4 vector path, 4 edges/thread ---------------
__device__ __forceinline__ void fill_one(int s, int d, int n) {
    if ((unsigned)s >= (unsigned)n || (unsigned)d >= (unsigned)n) return;
    int pos = atomicAdd(&g_cursor[d], 1);
    int idx = g_rowstart[d] + pos;
    if (idx < E_MAX) g_csrc[idx] = s;
}

__global__ void k_fill(const void* __restrict__ ei, int E, int n) {
    int t = blockIdx.x * blockDim.x + threadIdx.x;
    if (g_is32 && (E & 3) == 0) {
        const int4* s4 = (const int4*)ei;
        const int4* d4 = (const int4*)((const int*)ei + E);
        if (t < (E >> 2)) {
            int4 s = s4[t];
            int4 d = d4[t];
            fill_one(s.x, d.x, n);
            fill_one(s.y, d.y, n);
            fill_one(s.z, d.z, n);
            fill_one(s.w, d.w, n);
        }
    } else {
        long long e0 = (long long)t * 4;
        for (int j = 0; j < 4 && e0 + j < E; j++) {
            int s = edge_at(ei, e0 + j);
            int d = edge_at(ei, (long long)E + e0 + j);
            fill_one(s, d, n);
        }
    }
}

// ============ bf16x3 tensor-core GEMM via mma.sync (m16n8k16) ==============
__device__ __forceinline__ uint32_t pack_hi(float x, float y) {
    __nv_bfloat16 a = __float2bfloat16(x), b = __float2bfloat16(y);
    return ((uint32_t)__bfloat16_as_ushort(b) << 16) | __bfloat16_as_ushort(a);
}
__device__ __forceinline__ uint32_t pack_lo(float x, float y) {
    __nv_bfloat16 a = __float2bfloat16(x), b = __float2bfloat16(y);
    float rx = x - __bfloat162float(a), ry = y - __bfloat162float(b);
    __nv_bfloat16 c = __float2bfloat16(rx), d = __float2bfloat16(ry);
    return ((uint32_t)__bfloat16_as_ushort(d) << 16) | __bfloat16_as_ushort(c);
}

__device__ __forceinline__ void mma_bf16(float* d, uint32_t a0, uint32_t a1,
                                         uint32_t a2, uint32_t a3,
                                         uint32_t b0, uint32_t b1) {
    asm volatile(
        "mma.sync.aligned.m16n8k16.row.col.f32.bf16.bf16.f32 "
        "{%0,%1,%2,%3}, {%4,%5,%6,%7}, {%8,%9}, {%0,%1,%2,%3};"
        : "+f"(d[0]), "+f"(d[1]), "+f"(d[2]), "+f"(d[3])
        : "r"(a0), "r"(a1), "r"(a2), "r"(a3), "r"(b0), "r"(b1));
}

// HALF_OUT: write C to g_h1 as fp16. Else write g_h2 fp32 (c-select implicit).
// b_from_fold: use g_w2eff as B. a_from_agg1: A = g_agg1.
template <int N, bool RELU_BIAS, bool SCALE, bool HALF_OUT>
__global__ void __launch_bounds__(256)
k_gemm_mma(const float* __restrict__ Ain, const float* __restrict__ Bin,
           const float* __restrict__ bias, int a_from_agg1, int b_from_fold,
           int M) {
    constexpr int LD = N + 8;
    constexpr int NT = N / 8;
    __shared__ uint32_t sBh[32][LD];
    __shared__ uint32_t sBl[32][LD];

    const float* A = a_from_agg1 ? g_agg1 : Ain;
    const float* Bg = b_from_fold ? g_w2eff : Bin;

    const int tid = threadIdx.x;
    const int warp = tid >> 5, lane = tid & 31;
    const int g = lane >> 2, q = lane & 3;
    const int row0 = blockIdx.x * 128 + warp * 16 + g;
    const int row1 = row0 + 8;
    const bool v0 = row0 < M, v1 = row1 < M;

    float acc[NT][4];
#pragma unroll
    for (int c = 0; c < NT; c++)
#pragma unroll
        for (int i = 0; i < 4; i++) acc[c][i] = 0.f;

    const float* ar0 = A + (size_t)row0 * 128;
    const float* ar1 = A + (size_t)row1 * 128;

    for (int half = 0; half < 2; half++) {
        __syncthreads();
        for (int idx = tid; idx < 64 * N; idx += 256) {
            int k = idx / N;
            int nn = idx - k * N;
            float v = Bg[(size_t)(half * 64 + k) * N + nn];
            __nv_bfloat16 hi = __float2bfloat16(v);
            __nv_bfloat16 lo = __float2bfloat16(v - __bfloat162float(hi));
            ((unsigned short*)&sBh[k >> 1][nn])[k & 1] = __bfloat16_as_ushort(hi);
            ((unsigned short*)&sBl[k >> 1][nn])[k & 1] = __bfloat16_as_ushort(lo);
        }
        __syncthreads();

#pragma unroll
        for (int j = 0; j < 4; j++) {
            const int kb = half * 64 + j * 16;
            float2 p00 = make_float2(0.f, 0.f), p01 = p00, p10 = p00, p11 = p00;
            if (v0) { p00 = *(const float2*)(ar0 + kb + 2 * q);
                      p01 = *(const float2*)(ar0 + kb + 2 * q + 8); }
            if (v1) { p10 = *(const float2*)(ar1 + kb + 2 * q);
                      p11 = *(const float2*)(ar1 + kb + 2 * q + 8); }
            if (RELU_BIAS) {
                float2 bA = *(const float2*)(bias + kb + 2 * q);
                float2 bB = *(const float2*)(bias + kb + 2 * q + 8);
                p00.x = fmaxf(p00.x + bA.x, 0.f); p00.y = fmaxf(p00.y + bA.y, 0.f);
                p01.x = fmaxf(p01.x + bB.x, 0.f); p01.y = fmaxf(p01.y + bB.y, 0.f);
                p10.x = fmaxf(p10.x + bA.x, 0.f); p10.y = fmaxf(p10.y + bA.y, 0.f);
                p11.x = fmaxf(p11.x + bB.x, 0.f); p11.y = fmaxf(p11.y + bB.y, 0.f);
            }
            uint32_t ah0 = pack_hi(p00.x, p00.y), al0 = pack_lo(p00.x, p00.y);
            uint32_t ah1 = pack_hi(p10.x, p10.y), al1 = pack_lo(p10.x, p10.y);
            uint32_t ah2 = pack_hi(p01.x, p01.y), al2 = pack_lo(p01.x, p01.y);
            uint32_t ah3 = pack_hi(p11.x, p11.y), al3 = pack_lo(p11.x, p11.y);

            const int kp0 = j * 8 + q, kp1 = kp0 + 4;
#pragma unroll
            for (int c = 0; c < NT; c++) {
                int nn = c * 8 + g;
                uint32_t b0h = sBh[kp0][nn];
                uint32_t b1h = sBh[kp1][nn];
                uint32_t b0l = sBl[kp0][nn];
                uint32_t b1l = sBl[kp1][nn];
                mma_bf16(acc[c], ah0, ah1, ah2, ah3, b0h, b1h);
                mma_bf16(acc[c], ah0, ah1, ah2, ah3, b0l, b1l);
                mma_bf16(acc[c], al0, al1, al2, al3, b0h, b1h);
            }
        }
    }

    float s0 = 1.f, s1 = 1.f;
    if (SCALE) {
        s0 = v0 ? g_dinv[row0] : 0.f;
        s1 = v1 ? g_dinv[row1] : 0.f;
    }
#pragma unroll
    for (int c = 0; c < NT; c++) {
        int col = c * 8 + 2 * q;
        if (HALF_OUT) {
            if (v0) *(__half2*)(g_h1 + (size_t)row0 * N + col) =
                __floats2half2_rn(acc[c][0] * s0, acc[c][1] * s0);
            if (v1) *(__half2*)(g_h1 + (size_t)row1 * N + col) =
                __floats2half2_rn(acc[c][2] * s1, acc[c][3] * s1);
        } else {
            if (v0) *(float2*)(g_h2 + (size_t)row0 * N + col) =
                make_float2(acc[c][0] * s0, acc[c][1] * s0);
            if (v1) *(float2*)(g_h2 + (size_t)row1 * N + col) =
                make_float2(acc[c][2] * s1, acc[c][3] * s1);
        }
    }
}

// ---------------- CSR aggregation layer 1 (fp16 gather, fp32 accumulate) ---
// h1 RAW fp16; agg1[d] = dinv[d]*(dinv[d]*h1[d] + sum_e dinv[s]*h1[s]).
__device__ __forceinline__ float4 h4_to_f4(uint2 v) {
    float2 a = __half22float2(*(__half2*)&v.x);
    float2 b = __half22float2(*(__half2*)&v.y);
    return make_float4(a.x, a.y, b.x, b.y);
}

__global__ void k_agg128(int n) {
    const int lane = threadIdx.x & 31;
    const int warp = threadIdx.x >> 5;
    int node = blockIdx.x * (blockDim.x >> 5) + warp;
    if (node >= n) return;
    const uint2* __restrict__ hv = (const uint2*)g_h1;   // 8B = 4 fp16/lane
    const int* __restrict__ csrc = g_csrc;
    const float* __restrict__ dinv = g_dinv;

    float dd = dinv[node];
    float4 self = h4_to_f4(hv[(size_t)node * 32 + lane]);
    float4 acc;
    acc.x = self.x * dd; acc.y = self.y * dd;
    acc.z = self.z * dd; acc.w = self.w * dd;

    int e = g_rowstart[node], end = g_rowstart[node + 1];
    for (; e + 4 <= end; e += 4) {
        int s0 = csrc[e], s1 = csrc[e + 1], s2 = csrc[e + 2], s3 = csrc[e + 3];
        float c0 = dinv[s0], c1 = dinv[s1], c2 = dinv[s2], c3 = dinv[s3];
        uint2 r0 = hv[(size_t)s0 * 32 + lane];
        uint2 r1 = hv[(size_t)s1 * 32 + lane];
        uint2 r2 = hv[(size_t)s2 * 32 + lane];
        uint2 r3 = hv[(size_t)s3 * 32 + lane];
        float4 v0 = h4_to_f4(r0), v1 = h4_to_f4(r1);
        float4 v2 = h4_to_f4(r2), v3 = h4_to_f4(r3);
        acc.x += v0.x * c0 + v1.x * c1 + v2.x * c2 + v3.x * c3;
        acc.y += v0.y * c0 + v1.y * c1 + v2.y * c2 + v3.y * c3;
        acc.z += v0.z * c0 + v1.z * c1 + v2.z * c2 + v3.z * c3;
        acc.w += v0.w * c0 + v1.w * c1 + v2.w * c2 + v3.w * c3;
    }
    for (; e < end; e++) {
        int s0 = csrc[e];
        float c0 = dinv[s0];
        float4 v = h4_to_f4(hv[(size_t)s0 * 32 + lane]);
        acc.x += v.x * c0; acc.y += v.y * c0;
        acc.z += v.z * c0; acc.w += v.w * c0;
    }
    acc.x *= dd; acc.y *= dd; acc.z *= dd; acc.w *= dd;
    // agg1 fp32, lane holds features 4*lane..+3
    ((float4*)g_agg1)[(size_t)node * 32 + lane] = acc;
}

// -------- FUSED layer-2 aggregation + beff + log_softmax -> out ------------
__global__ void k_aggout(float* __restrict__ out, int n) {
    const int lane16 = threadIdx.x & 15;
    const int half = threadIdx.x >> 4;
    int node = blockIdx.x * (blockDim.x >> 4) + half;
    if (node >= n) return;
    const float4* __restrict__ hv = (const float4*)g_h2;
    const int* __restrict__ csrc = g_csrc;

    float4 acc = hv[(size_t)node * 16 + lane16];   // self (pre-scaled)
    int e = g_rowstart[node], end = g_rowstart[node + 1];
    for (; e + 4 <= end; e += 4) {
        int s0 = csrc[e], s1 = csrc[e + 1], s2 = csrc[e + 2], s3 = csrc[e + 3];
        float4 v0 = hv[(size_t)s0 * 16 + lane16];
        float4 v1 = hv[(size_t)s1 * 16 + lane16];
        float4 v2 = hv[(size_t)s2 * 16 + lane16];
        float4 v3 = hv[(size_t)s3 * 16 + lane16];
        acc.x += (v0.x + v1.x) + (v2.x + v3.x);
        acc.y += (v0.y + v1.y) + (v2.y + v3.y);
        acc.z += (v0.z + v1.z) + (v2.z + v3.z);
        acc.w += (v0.w + v1.w) + (v2.w + v3.w);
    }
    for (; e < end; e++) {
        float4 v = hv[(size_t)csrc[e] * 16 + lane16];
        acc.x += v.x; acc.y += v.y; acc.z += v.z; acc.w += v.w;
    }
    float dd = g_dinv[node];
    float4 be = ((const float4*)g_beff)[lane16];
    float4 lg;
    lg.x = acc.x * dd + be.x;
    lg.y = acc.y * dd + be.y;
    lg.z = acc.z * dd + be.z;
    lg.w = acc.w * dd + be.w;

    float m = fmaxf(fmaxf(lg.x, lg.y), fmaxf(lg.z, lg.w));
#pragma unroll
    for (int off = 8; off; off >>= 1)
        m = fmaxf(m, __shfl_xor_sync(0xffffffffu, m, off, 16));
    float s = expf(lg.x - m) + expf(lg.y - m) + expf(lg.z - m) + expf(lg.w - m);
#pragma unroll
    for (int off = 8; off; off >>= 1)
        s += __shfl_xor_sync(0xffffffffu, s, off, 16);
    float lse = m + logf(s);
    float4 o = make_float4(lg.x - lse, lg.y - lse, lg.z - lse, lg.w - lse);
    ((float4*)out)[(size_t)node * 16 + lane16] = o;
}

// ---------------- launcher (fork-join: [fold+gemm1] || CSR build) ----------
extern "C" void kernel_launch(void* const* d_in, const int* in_sizes, int n_in,
                              void* d_out, int out_size) {
    const float* x    = (const float*)d_in[0];
    const void*  ei   = d_in[1];
    const float* W1   = (const float*)d_in[2];
    const float* b1   = (const float*)d_in[3];
    const float* W2   = (const float*)d_in[4];
    const float* b2   = (const float*)d_in[5];
    const float* linW = (const float*)d_in[6];
    const float* linb = (const float*)d_in[7];
    float* out = (float*)d_out;

    const int n = in_sizes[0] / C_IN;
    const int E = in_sizes[1] / 2;
    const int nb = (n + SCAN_TILE - 1) / SCAN_TILE;

    cudaStream_t s2;
    cudaEvent_t evFork, evJoin;
    cudaStreamCreateWithFlags(&s2, cudaStreamNonBlocking);
    cudaEventCreateWithFlags(&evFork, cudaEventDisableTiming);
    cudaEventCreateWithFlags(&evJoin, cudaEventDisableTiming);

    // ---- fork: weight fold + gemm1 run on s2 (both independent of CSR/deg)
    cudaEventRecord(evFork, 0);
    cudaStreamWaitEvent(s2, evFork, 0);
    k_fold<<<(C_HID * C_OUT + 255) / 256, 256, 0, s2>>>(W2, b2, linW, linb);
    k_gemm_mma<C_HID, false, false, true><<<(n + 127) / 128, 256, 0, s2>>>(
        x, W1, nullptr, 0, 0, n);
    cudaEventRecord(evJoin, s2);

    // ---- main stream: CSR build chain
    k_init<<<(n + 255) / 256, 256>>>(ei, E, n);
    k_deg_count<<<(E + 2047) / 2048, 256>>>(ei, E, n);
    k_scan1<<<nb, 256>>>(n);
    k_scan2<<<1, 256>>>(nb, n);
    k_scan3<<<nb, 256>>>(n);
    k_fill<<<(E + 1023) / 1024, 256>>>(ei, E, n);

    // ---- join: aggregation needs h1 + CSR + dinv (fold done on s2)
    cudaStreamWaitEvent(0, evJoin, 0);
    k_agg128<<<(n + 7) / 8, 256>>>(n);

    // layer 2: h2 = (relu(agg1+b1) @ W2eff)*dinv ; fused agg + softmax -> out
    k_gemm_mma<C_OUT, true, true, false><<<(n + 127) / 128, 256>>>(
        nullptr, nullptr, b1, 1, 1, n);
    k_aggout<<<(n + 15) / 16, 256>>>(out, n);

    cudaEventDestroy(evFork);
    cudaEventDestroy(evJoin);
    cudaStreamDestroy(s2);
}